// round 12
// baseline (speedup 1.0000x reference)
#include <cuda_runtime.h>
#include <math.h>

// Hyperbolic_Lines: out = sum_i acosh(1 + d2_i)^2
//   d2_i = ||y_i||^2 - (y_i . w)^2 / ||w||^2
//
// HBM-bound streaming reduction over y (256 MB).
// 8 lanes per row; 8 LDG.128 front-batched per warp iteration (MLP=8).
// R12: revert to 1184-block oversubscribed grid (2-wave streaming -> dynamic
// SM load balancing; the R11 single-wave static partition cost ~8% DRAM) and
// plain loads (drop __ldcs). Keep the fused last-block final reduction
// (no init kernel, graph-replay-safe self-resetting counter).

#define DCOLS 128
#define THREADS_PER_BLOCK 256
#define WARPS_PER_BLOCK (THREADS_PER_BLOCK / 32)
#define GRID_BLOCKS 1184   // 148 SMs * 8 blocks: 2 waves at occ 4 -> balancing

__device__ float        g_partials[GRID_BLOCKS];
__device__ unsigned int g_done = 0;   // reset to 0 by the last block each launch

__device__ __forceinline__ float dot4(float4 a, float4 b) {
    return a.x * b.x + a.y * b.y + a.z * b.z + a.w * b.w;
}

__global__ __launch_bounds__(THREADS_PER_BLOCK, 4)
void hl_main_kernel(const float* __restrict__ w,
                    const float* __restrict__ y,
                    float* __restrict__ out,
                    int n_rows) {
    const int lane = threadIdx.x & 31;
    const int sub  = lane & 7;    // position within 8-lane row-group
    const int grp  = lane >> 3;   // which of 4 rows this lane serves
    const int warp = threadIdx.x >> 5;
    const int gwarp = blockIdx.x * WARPS_PER_BLOCK + warp;
    const int total_warps = GRID_BLOCKS * WARPS_PER_BLOCK;

    const float4* __restrict__ w4p = reinterpret_cast<const float4*>(w);
    const float4* __restrict__ y4p = reinterpret_cast<const float4*>(y);

    // w chunk for this sublane: float4 indices sub + 8k (16 floats, in regs).
    float4 wv0 = w4p[sub + 0];
    float4 wv1 = w4p[sub + 8];
    float4 wv2 = w4p[sub + 16];
    float4 wv3 = w4p[sub + 24];

    // ||w||^2: partial over this lane's 16 elements, butterfly within group.
    float nw2 = dot4(wv0, wv0) + dot4(wv1, wv1) + dot4(wv2, wv2) + dot4(wv3, wv3);
    nw2 += __shfl_xor_sync(0xFFFFFFFFu, nw2, 1);
    nw2 += __shfl_xor_sync(0xFFFFFFFFu, nw2, 2);
    nw2 += __shfl_xor_sync(0xFFFFFFFFu, nw2, 4);
    const float inv_nw2 = 1.0f / nw2;

    float acc = 0.0f;  // real values only on sublane-0 lanes

    const int stride = total_warps * 8;
    const int n_full = n_rows & ~7;   // multiple of 8 (== n_rows for N=500000)

    // ---- Fast path: all 8 rows of the group in bounds, no predicates. ----
    for (int base = gwarp * 8; base + 8 <= n_full; base += stride) {
        const float4* pa = y4p + ((size_t)(base + grp)) * 32 + sub;
        const float4* pb = pa + 4 * 32;

        // Batch all 8 loads up front (MLP=8 per warp).
        float4 a0 = pa[0], a1 = pa[8], a2 = pa[16], a3 = pa[24];
        float4 b0 = pb[0], b1 = pb[8], b2 = pb[16], b3 = pb[24];

        float s1a = dot4(a0, a0) + dot4(a1, a1) + dot4(a2, a2) + dot4(a3, a3);
        float s2a = dot4(a0, wv0) + dot4(a1, wv1) + dot4(a2, wv2) + dot4(a3, wv3);
        float s1b = dot4(b0, b0) + dot4(b1, b1) + dot4(b2, b2) + dot4(b3, b3);
        float s2b = dot4(b0, wv0) + dot4(b1, wv1) + dot4(b2, wv2) + dot4(b3, wv3);

        #pragma unroll
        for (int off = 1; off <= 4; off <<= 1) {
            s1a += __shfl_xor_sync(0xFFFFFFFFu, s1a, off);
            s2a += __shfl_xor_sync(0xFFFFFFFFu, s2a, off);
            s1b += __shfl_xor_sync(0xFFFFFFFFu, s1b, off);
            s2b += __shfl_xor_sync(0xFFFFFFFFu, s2b, off);
        }

        if (sub == 0) {
            float d2a = s1a - s2a * s2a * inv_nw2;
            float d2b = s1b - s2b * s2b * inv_nw2;
            float xa = 1.0f + d2a;
            float xb = 1.0f + d2b;
            float ta = __logf(xa + sqrtf(xa * xa - 1.0f));
            float tb = __logf(xb + sqrtf(xb * xb - 1.0f));
            acc += ta * ta + tb * tb;
        }
    }

    // ---- Tail: remaining rows (none for N=500000). ----
    if (n_full < n_rows && gwarp == 0) {
        for (int base = n_full; base < n_rows; base += 4) {
            const int r = base + grp;
            float s1 = 0.0f, s2 = 0.0f;
            if (r < n_rows) {
                const float4* p = y4p + (size_t)r * 32 + sub;
                float4 a0 = p[0], a1 = p[8], a2 = p[16], a3 = p[24];
                s1 = dot4(a0, a0) + dot4(a1, a1) + dot4(a2, a2) + dot4(a3, a3);
                s2 = dot4(a0, wv0) + dot4(a1, wv1) + dot4(a2, wv2) + dot4(a3, wv3);
            }
            #pragma unroll
            for (int off = 1; off <= 4; off <<= 1) {
                s1 += __shfl_xor_sync(0xFFFFFFFFu, s1, off);
                s2 += __shfl_xor_sync(0xFFFFFFFFu, s2, off);
            }
            if (sub == 0 && r < n_rows) {
                float d2 = s1 - s2 * s2 * inv_nw2;
                float x = 1.0f + d2;
                float t = __logf(x + sqrtf(x * x - 1.0f));
                acc += t * t;
            }
        }
    }

    // ---- Block reduction -> per-block partial. ----
    #pragma unroll
    for (int off = 16; off > 0; off >>= 1)
        acc += __shfl_xor_sync(0xFFFFFFFFu, acc, off);

    __shared__ float warp_sums[WARPS_PER_BLOCK];
    __shared__ bool  is_last;
    if (lane == 0) warp_sums[warp] = acc;
    __syncthreads();

    if (threadIdx.x == 0) {
        float bsum = 0.0f;
        #pragma unroll
        for (int i = 0; i < WARPS_PER_BLOCK; i++) bsum += warp_sums[i];
        g_partials[blockIdx.x] = bsum;
        __threadfence();
        unsigned prev = atomicAdd(&g_done, 1u);
        is_last = (prev == (unsigned)(GRID_BLOCKS - 1));
    }
    __syncthreads();

    // ---- Last block: reduce all partials, write output, reset counter. ----
    if (is_last) {
        __threadfence();  // order partial reads after all blocks' fenced writes
        float v = 0.0f;
        for (int i = threadIdx.x; i < GRID_BLOCKS; i += THREADS_PER_BLOCK)
            v += g_partials[i];
        #pragma unroll
        for (int off = 16; off > 0; off >>= 1)
            v += __shfl_xor_sync(0xFFFFFFFFu, v, off);
        if (lane == 0) warp_sums[warp] = v;
        __syncthreads();
        if (threadIdx.x == 0) {
            float total = 0.0f;
            #pragma unroll
            for (int i = 0; i < WARPS_PER_BLOCK; i++) total += warp_sums[i];
            out[0] = total;
            g_done = 0;   // leave clean state for the next (graph-replayed) launch
        }
    }
}

extern "C" void kernel_launch(void* const* d_in, const int* in_sizes, int n_in,
                              void* d_out, int out_size) {
    const float* w = (const float*)d_in[0];   // [128]
    const float* y = (const float*)d_in[1];   // [500000, 128]
    float* out = (float*)d_out;

    const int n_rows = in_sizes[1] / DCOLS;

    hl_main_kernel<<<GRID_BLOCKS, THREADS_PER_BLOCK>>>(w, y, out, n_rows);
}

// round 14
// speedup vs baseline: 1.0713x; 1.0713x over previous
#include <cuda_runtime.h>
#include <math.h>

// Hyperbolic_Lines: out = sum_i acosh(1 + d2_i)^2
//   d2_i = ||y_i||^2 - (y_i . w)^2 / ||w||^2
//
// HBM-bound streaming reduction over y (256 MB).
// 8 lanes per row; 8 LDG.128 front-batched per warp iteration (MLP=8).
// R13: persistent single-wave grid (592 blocks) + DYNAMIC WORK-STEALING:
// blocks grab 64-row chunks from a global atomic counter. Removes the
// 7-vs-6.6 iteration quantization (~6% critical path) and balances across
// slow/fast SMs. Fused last-block final reduction; counters self-reset
// for graph replay.

#define DCOLS 128
#define THREADS_PER_BLOCK 256
#define WARPS_PER_BLOCK (THREADS_PER_BLOCK / 32)
#define GRID_BLOCKS 592        // 148 SMs * 4 resident blocks, single wave
#define ROWS_PER_CHUNK 64      // 8 warps * 8 rows

__device__ float        g_partials[GRID_BLOCKS];
__device__ unsigned int g_next = 0;   // work-stealing cursor (reset each launch)
__device__ unsigned int g_done = 0;   // completion counter (reset each launch)

__device__ __forceinline__ float dot4(float4 a, float4 b) {
    return a.x * b.x + a.y * b.y + a.z * b.z + a.w * b.w;
}

__global__ __launch_bounds__(THREADS_PER_BLOCK, 4)
void hl_main_kernel(const float* __restrict__ w,
                    const float* __restrict__ y,
                    float* __restrict__ out,
                    int n_rows) {
    const int lane = threadIdx.x & 31;
    const int sub  = lane & 7;    // position within 8-lane row-group
    const int grp  = lane >> 3;   // which of 4 rows this lane serves
    const int warp = threadIdx.x >> 5;

    const float4* __restrict__ w4p = reinterpret_cast<const float4*>(w);
    const float4* __restrict__ y4p = reinterpret_cast<const float4*>(y);

    // w chunk for this sublane: float4 indices sub + 8k (16 floats, in regs).
    float4 wv0 = w4p[sub + 0];
    float4 wv1 = w4p[sub + 8];
    float4 wv2 = w4p[sub + 16];
    float4 wv3 = w4p[sub + 24];

    // ||w||^2: partial over this lane's 16 elements, butterfly within group.
    float nw2 = dot4(wv0, wv0) + dot4(wv1, wv1) + dot4(wv2, wv2) + dot4(wv3, wv3);
    nw2 += __shfl_xor_sync(0xFFFFFFFFu, nw2, 1);
    nw2 += __shfl_xor_sync(0xFFFFFFFFu, nw2, 2);
    nw2 += __shfl_xor_sync(0xFFFFFFFFu, nw2, 4);
    const float inv_nw2 = 1.0f / nw2;

    float acc = 0.0f;  // real values only on sublane-0 lanes

    const unsigned n_chunks = (unsigned)((n_rows + ROWS_PER_CHUNK - 1) / ROWS_PER_CHUNK);

    __shared__ unsigned s_chunk;

    for (;;) {
        if (threadIdx.x == 0) s_chunk = atomicAdd(&g_next, 1u);
        __syncthreads();
        const unsigned chunk = s_chunk;
        __syncthreads();   // protect s_chunk before tid0's next write
        if (chunk >= n_chunks) break;

        const int row0 = (int)chunk * ROWS_PER_CHUNK + warp * 8;

        if (row0 + 8 <= n_rows) {
            // ---- Fast path: all 8 rows in bounds, no predicates. ----
            const float4* pa = y4p + ((size_t)(row0 + grp)) * 32 + sub;
            const float4* pb = pa + 4 * 32;

            // Batch all 8 loads up front (MLP=8 per warp).
            float4 a0 = pa[0], a1 = pa[8], a2 = pa[16], a3 = pa[24];
            float4 b0 = pb[0], b1 = pb[8], b2 = pb[16], b3 = pb[24];

            float s1a = dot4(a0, a0) + dot4(a1, a1) + dot4(a2, a2) + dot4(a3, a3);
            float s2a = dot4(a0, wv0) + dot4(a1, wv1) + dot4(a2, wv2) + dot4(a3, wv3);
            float s1b = dot4(b0, b0) + dot4(b1, b1) + dot4(b2, b2) + dot4(b3, b3);
            float s2b = dot4(b0, wv0) + dot4(b1, wv1) + dot4(b2, wv2) + dot4(b3, wv3);

            #pragma unroll
            for (int off = 1; off <= 4; off <<= 1) {
                s1a += __shfl_xor_sync(0xFFFFFFFFu, s1a, off);
                s2a += __shfl_xor_sync(0xFFFFFFFFu, s2a, off);
                s1b += __shfl_xor_sync(0xFFFFFFFFu, s1b, off);
                s2b += __shfl_xor_sync(0xFFFFFFFFu, s2b, off);
            }

            if (sub == 0) {
                float d2a = s1a - s2a * s2a * inv_nw2;
                float d2b = s1b - s2b * s2b * inv_nw2;
                float xa = 1.0f + d2a;
                float xb = 1.0f + d2b;
                float ta = __logf(xa + sqrtf(xa * xa - 1.0f));
                float tb = __logf(xb + sqrtf(xb * xb - 1.0f));
                acc += ta * ta + tb * tb;
            }
        } else if (row0 < n_rows) {
            // ---- Guarded path: only the final partial chunk lands here. ----
            const int ra = row0 + grp;
            const int rb = ra + 4;
            const float4 z = make_float4(0.f, 0.f, 0.f, 0.f);
            float4 a0 = z, a1 = z, a2 = z, a3 = z;
            float4 b0 = z, b1 = z, b2 = z, b3 = z;
            if (ra < n_rows) {
                const float4* p = y4p + (size_t)ra * 32 + sub;
                a0 = p[0]; a1 = p[8]; a2 = p[16]; a3 = p[24];
            }
            if (rb < n_rows) {
                const float4* p = y4p + (size_t)rb * 32 + sub;
                b0 = p[0]; b1 = p[8]; b2 = p[16]; b3 = p[24];
            }

            float s1a = dot4(a0, a0) + dot4(a1, a1) + dot4(a2, a2) + dot4(a3, a3);
            float s2a = dot4(a0, wv0) + dot4(a1, wv1) + dot4(a2, wv2) + dot4(a3, wv3);
            float s1b = dot4(b0, b0) + dot4(b1, b1) + dot4(b2, b2) + dot4(b3, b3);
            float s2b = dot4(b0, wv0) + dot4(b1, wv1) + dot4(b2, wv2) + dot4(b3, wv3);

            #pragma unroll
            for (int off = 1; off <= 4; off <<= 1) {
                s1a += __shfl_xor_sync(0xFFFFFFFFu, s1a, off);
                s2a += __shfl_xor_sync(0xFFFFFFFFu, s2a, off);
                s1b += __shfl_xor_sync(0xFFFFFFFFu, s1b, off);
                s2b += __shfl_xor_sync(0xFFFFFFFFu, s2b, off);
            }

            if (sub == 0) {
                // OOB rows contribute s1=s2=0 -> x=1 -> acosh=0.
                float d2a = s1a - s2a * s2a * inv_nw2;
                float d2b = s1b - s2b * s2b * inv_nw2;
                float xa = 1.0f + d2a;
                float xb = 1.0f + d2b;
                float ta = __logf(xa + sqrtf(xa * xa - 1.0f));
                float tb = __logf(xb + sqrtf(xb * xb - 1.0f));
                acc += ta * ta + tb * tb;
            }
        }
        // rows entirely OOB for this warp: nothing to do.
    }

    // ---- Block reduction -> per-block partial. ----
    #pragma unroll
    for (int off = 16; off > 0; off >>= 1)
        acc += __shfl_xor_sync(0xFFFFFFFFu, acc, off);

    __shared__ float warp_sums[WARPS_PER_BLOCK];
    __shared__ bool  is_last;
    if (lane == 0) warp_sums[warp] = acc;
    __syncthreads();

    if (threadIdx.x == 0) {
        float bsum = 0.0f;
        #pragma unroll
        for (int i = 0; i < WARPS_PER_BLOCK; i++) bsum += warp_sums[i];
        g_partials[blockIdx.x] = bsum;
        __threadfence();
        unsigned prev = atomicAdd(&g_done, 1u);
        is_last = (prev == (unsigned)(GRID_BLOCKS - 1));
    }
    __syncthreads();

    // ---- Last block: reduce partials, write output, reset counters. ----
    if (is_last) {
        __threadfence();  // order partial reads after all blocks' fenced writes
        float v = 0.0f;
        for (int i = threadIdx.x; i < GRID_BLOCKS; i += THREADS_PER_BLOCK)
            v += g_partials[i];
        #pragma unroll
        for (int off = 16; off > 0; off >>= 1)
            v += __shfl_xor_sync(0xFFFFFFFFu, v, off);
        if (lane == 0) warp_sums[warp] = v;
        __syncthreads();
        if (threadIdx.x == 0) {
            float total = 0.0f;
            #pragma unroll
            for (int i = 0; i < WARPS_PER_BLOCK; i++) total += warp_sums[i];
            out[0] = total;
            g_done = 0;   // reset for next graph replay
            g_next = 0;
        }
    }
}

extern "C" void kernel_launch(void* const* d_in, const int* in_sizes, int n_in,
                              void* d_out, int out_size) {
    const float* w = (const float*)d_in[0];   // [128]
    const float* y = (const float*)d_in[1];   // [500000, 128]
    float* out = (float*)d_out;

    const int n_rows = in_sizes[1] / DCOLS;

    hl_main_kernel<<<GRID_BLOCKS, THREADS_PER_BLOCK>>>(w, y, out, n_rows);
}